// round 15
// baseline (speedup 1.0000x reference)
#include <cuda_runtime.h>
#include <cuda_bf16.h>
#include <cstdint>

// ---------------------------------------------------------------------------
// B=256, T=512, I=64, H=256, 2-layer bidirectional LSTM, FC on last timestep.
// R15: GEMM now 512 threads (16 warps, 4/SMSP) on the same 128x128 tile --
//      doubles latency hiding on the LDS->MMA dependency stalls (the same fix
//      that won R5 for the recurrence). Warp tile 32n x 32m, acc 32/thread.
//      Everything else identical to R14.
// ---------------------------------------------------------------------------

__device__ float    g_xT  [512 * 64 * 256];
__device__ float    g_xp0f[512 * 1024 * 256];
__device__ float    g_xp0r[512 * 1024 * 256];
__device__ float    g_h0c [512 * 512 * 256];
__device__ float    g_xp1f[512 * 1024 * 256];
__device__ float    g_xp1r[1024 * 256];
__device__ float    g_h1  [512 * 256 * 256];
__device__ uint32_t g_hhi [512 * 2 * 128 * 256];   // h packed bf16x2 hi
__device__ uint32_t g_hlo [512 * 2 * 128 * 256];   // h packed bf16x2 lo
__device__ float    g_wt  [1024 * (64 + 64 + 512 + 512)];  // tf32-rounded W_ih's

__device__ unsigned g_gcnt [32 * 32];
__device__ unsigned g_ggen [32 * 32];
__device__ unsigned g_flags[16 * 32];

__device__ __forceinline__ float sigm(float x) { return 1.0f / (1.0f + __expf(-x)); }

__device__ __forceinline__ uint32_t f2tf32(float x) {
    uint32_t r;
    asm("cvt.rna.tf32.f32 %0, %1;" : "=r"(r) : "f"(x));
    return r;
}

__device__ __forceinline__ void mma_tf32(float c[4], const uint32_t a[4], const uint32_t b[2]) {
    asm volatile(
        "mma.sync.aligned.m16n8k8.row.col.f32.tf32.tf32.f32 "
        "{%0,%1,%2,%3}, {%4,%5,%6,%7}, {%8,%9}, {%0,%1,%2,%3};"
        : "+f"(c[0]), "+f"(c[1]), "+f"(c[2]), "+f"(c[3])
        : "r"(a[0]), "r"(a[1]), "r"(a[2]), "r"(a[3]), "r"(b[0]), "r"(b[1]));
}

__device__ __forceinline__ void mma_bf16(float c[4], const uint32_t a[4], const uint32_t b[2]) {
    asm volatile(
        "mma.sync.aligned.m16n8k16.row.col.f32.bf16.bf16.f32 "
        "{%0,%1,%2,%3}, {%4,%5,%6,%7}, {%8,%9}, {%0,%1,%2,%3};"
        : "+f"(c[0]), "+f"(c[1]), "+f"(c[2]), "+f"(c[3])
        : "r"(a[0]), "r"(a[1]), "r"(a[2]), "r"(a[3]), "r"(b[0]), "r"(b[1]));
}

__device__ __forceinline__ uint32_t packbf2(float a, float b) {
    __nv_bfloat162 t = __floats2bfloat162_rn(a, b);
    return *(uint32_t*)&t;
}

__device__ __forceinline__ void cp_async16(void* smem_dst, const void* gptr) {
    uint32_t sa = (uint32_t)__cvta_generic_to_shared(smem_dst);
    asm volatile("cp.async.cg.shared.global [%0], [%1], 16;" :: "r"(sa), "l"(gptr));
}
__device__ __forceinline__ void cp_commit() { asm volatile("cp.async.commit_group;"); }
template <int N>
__device__ __forceinline__ void cp_wait() { asm volatile("cp.async.wait_group %0;" :: "n"(N)); }

// Proven acquire/release atomic group barrier — used ONCE per launch.
__device__ __forceinline__ void group_barrier_atomic(int grp, unsigned members) {
    __syncthreads();
    if (threadIdx.x == 0) {
        unsigned* cnt = &g_gcnt[grp * 32];
        unsigned* gen = &g_ggen[grp * 32];
        unsigned g0;
        asm volatile("ld.acquire.gpu.u32 %0, [%1];" : "=r"(g0) : "l"(gen));
        unsigned old;
        asm volatile("atom.acq_rel.gpu.add.u32 %0, [%1], 1;" : "=r"(old) : "l"(cnt));
        if (old == members - 1) {
            asm volatile("st.relaxed.gpu.u32 [%0], %1;" :: "l"(cnt), "r"(0u));
            asm volatile("red.release.gpu.add.u32 [%0], %1;" :: "l"(gen), "r"(1u));
        } else {
            unsigned g1;
            do {
                asm volatile("ld.acquire.gpu.u32 %0, [%1];" : "=r"(g1) : "l"(gen));
            } while (g1 == g0);
        }
    }
    __syncthreads();
}

// ---------------------------------------------------------------------------
// Transpose + tf32-round: x[b][t*64+k] -> xT[(t*64+k)][b]
// ---------------------------------------------------------------------------
__global__ void transpose_x(const float* __restrict__ x, float* __restrict__ xT) {
    __shared__ float tile[32][33];
    int c0 = blockIdx.x * 32, r0 = blockIdx.y * 32;
    int tx = threadIdx.x, ty = threadIdx.y;
#pragma unroll
    for (int i = 0; i < 32; i += 8)
        tile[ty + i][tx] = x[(size_t)(r0 + ty + i) * 32768 + c0 + tx];
    __syncthreads();
#pragma unroll
    for (int i = 0; i < 32; i += 8)
        xT[(size_t)(c0 + ty + i) * 256 + r0 + tx] =
            __uint_as_float(f2tf32(tile[tx][ty + i]));
}

// tf32-round a buffer (weight pre-conversion)
__global__ void cvt_tf32(const float* __restrict__ in, float* __restrict__ out, int n) {
    int i = blockIdx.x * 256 + threadIdx.x;
    if (i < n) out[i] = __uint_as_float(f2tf32(in[i]));
}

// ---------------------------------------------------------------------------
// TF32 GEMM v3: 512 threads, 128n x 128m tile, warp tile 32n x 32m,
// pre-rounded inputs, 3-stage cp.async pipeline, 1 sync/iter.
// Grid = (N/128, M/128, T). C[t][n][m] = W[n][k]*A[t][k][m] + b1[n] + b2[n]
// ---------------------------------------------------------------------------
#define WS_STRIDE 20
#define AS_STRIDE 132
#define GEMM_SMEM ((3 * 128 * WS_STRIDE + 3 * 16 * AS_STRIDE) * 4)   // 56064 B

__global__ void gemm_tf32(const float* __restrict__ A, const float* __restrict__ W,
                          const float* __restrict__ b1, const float* __restrict__ b2,
                          float* __restrict__ C, int K, int N) {
    extern __shared__ uint32_t gsm[];
    uint32_t* WsBase = gsm;                              // [3][128*20]
    uint32_t* AsBase = gsm + 3 * 128 * WS_STRIDE;        // [3][16*132]

    int t  = blockIdx.z;
    int n0 = blockIdx.x * 128, m0 = blockIdx.y * 128;
    const float* At = A + (size_t)t * K * 256 + m0;
    const float* Wt = W + (size_t)n0 * K;
    float* Ct = C + (size_t)t * N * 256;

    int tid = threadIdx.x;
    int warp = tid >> 5, lane = tid & 31;
    int wn = (warp >> 2) * 32;    // n-origin: 0,32,64,96
    int wb = (warp & 3) * 32;     // m-origin: 0,32,64,96
    int lr = lane >> 2, lc = lane & 3;

    // staging maps (512 threads; full coverage, 16B-aligned)
    int a_kk = tid >> 5, a_b4 = (tid & 31) * 4;   // A: 16 rows x 128, 1 chunk/thread
    int w_n  = tid >> 2, w_k4 = (tid & 3) * 4;    // W: 128 rows x 16,  1 chunk/thread

    float acc[2][4][4];
#pragma unroll
    for (int i = 0; i < 2; i++)
#pragma unroll
        for (int jj = 0; jj < 4; jj++)
#pragma unroll
            for (int r = 0; r < 4; r++) acc[i][jj][r] = 0.0f;

    auto stage = [&](int buf, int k0) {
        uint32_t* Asb = AsBase + buf * 16 * AS_STRIDE;
        uint32_t* Wsb = WsBase + buf * 128 * WS_STRIDE;
        cp_async16(&Asb[a_kk * AS_STRIDE + a_b4],
                   &At[(size_t)(k0 + a_kk) * 256 + a_b4]);
        cp_async16(&Wsb[w_n * WS_STRIDE + w_k4],
                   &Wt[(size_t)w_n * K + k0 + w_k4]);
    };

    int niter = K / 16;
    stage(0, 0);
    cp_commit();
    if (niter > 1) { stage(1, 16); cp_commit(); }

    for (int it = 0; it < niter; it++) {
        int buf = it % 3;
        if (it + 1 < niter) cp_wait<1>(); else cp_wait<0>();
        __syncthreads();

        uint32_t* Asb = AsBase + buf * 16 * AS_STRIDE;
        uint32_t* Wsb = WsBase + buf * 128 * WS_STRIDE;
#pragma unroll
        for (int ks = 0; ks < 2; ks++) {
            int kk = ks * 8;
            uint32_t a[2][4], b[4][2];
#pragma unroll
            for (int ni = 0; ni < 2; ni++) {
                int n = wn + ni * 16 + lr;
                a[ni][0] = Wsb[n * WS_STRIDE + kk + lc];
                a[ni][1] = Wsb[(n + 8) * WS_STRIDE + kk + lc];
                a[ni][2] = Wsb[n * WS_STRIDE + kk + lc + 4];
                a[ni][3] = Wsb[(n + 8) * WS_STRIDE + kk + lc + 4];
            }
#pragma unroll
            for (int bi = 0; bi < 4; bi++) {
                int bb = wb + bi * 8 + lr;
                b[bi][0] = Asb[(kk + lc) * AS_STRIDE + bb];
                b[bi][1] = Asb[(kk + lc + 4) * AS_STRIDE + bb];
            }
#pragma unroll
            for (int ni = 0; ni < 2; ni++)
#pragma unroll
                for (int bi = 0; bi < 4; bi++)
                    mma_tf32(acc[ni][bi], a[ni], b[bi]);
        }

        if (it + 2 < niter) {
            stage((it + 2) % 3, (it + 2) * 16);
            cp_commit();
        }
    }

#pragma unroll
    for (int ni = 0; ni < 2; ni++) {
#pragma unroll
        for (int h = 0; h < 2; h++) {
            int n = n0 + wn + ni * 16 + lr + h * 8;
            float bias = b1[n] + b2[n];
#pragma unroll
            for (int bi = 0; bi < 4; bi++) {
                int bb = m0 + wb + bi * 8 + lc * 2;
                float2 v = make_float2(acc[ni][bi][h * 2] + bias,
                                       acc[ni][bi][h * 2 + 1] + bias);
                *(float2*)&Ct[(size_t)n * 256 + bb] = v;
            }
        }
    }
}

// ---------------------------------------------------------------------------
// bf16 tensor-core persistent recurrence (unchanged from R12/R14).
// ---------------------------------------------------------------------------
#define WS2  132
#define HS2B 40
#define RGS2 36

template <int NDIR>
__global__ void __launch_bounds__(512, 1)
lstm_rec_mma(const float* __restrict__ xp_f, const float* __restrict__ xp_r,
             const float* __restrict__ whh_f, const float* __restrict__ whh_r,
             float* __restrict__ hout,
             uint32_t* __restrict__ hhi, uint32_t* __restrict__ hlo) {
    constexpr int NG = 8, BGN = 8;
    constexpr int HOUT_ROWS = NDIR * 256;

    extern __shared__ char smraw[];
    uint32_t* W2hi = (uint32_t*)smraw;
    uint32_t* W2lo = W2hi + 128 * WS2;
    uint32_t* H2hi = W2lo + 128 * WS2;
    uint32_t* H2lo = H2hi + 128 * HS2B;
    float*    gsh  = (float*)(H2lo + 128 * HS2B);

    int tid = threadIdx.x;
    int bx  = blockIdx.x;
    int dir = (NDIR == 2) ? (bx / (NG * BGN)) : 0;
    int rem = bx % (NG * BGN);
    int ng = rem / BGN, bg = rem % BGN;
    int u0 = ng * 32, b0 = bg * 32;
    int grp = dir * BGN + bg;

    const float* xp  = dir ? xp_r : xp_f;
    const float* whh = dir ? whh_r : whh_f;

    for (int i = tid; i < 128 * 128; i += 512) {
        int r = i >> 7, kp = i & 127;
        int grow = (r >> 5) * 256 + u0 + (r & 31);
        float2 w = *(const float2*)&whh[(size_t)grow * 256 + 2 * kp];
        uint32_t hi = packbf2(w.x, w.y);
        __nv_bfloat162 hb = *(__nv_bfloat162*)&hi;
        W2hi[r * WS2 + kp] = hi;
        W2lo[r * WS2 + kp] = packbf2(w.x - __low2float(hb), w.y - __high2float(hb));
    }

    int warp = tid >> 5, lane = tid & 31;
    int rbase = (warp & 7) * 16;
    int bbase = (warp >> 3) * 16;
    int lr = lane >> 2, lc = lane & 3;

    int j  = tid >> 5;
    int ub = tid & 31;
    float cr0 = 0.f, cr1 = 0.f;

    unsigned* myflag = &g_flags[grp * 32 + ng];
    unsigned memb_base = 0, my_base = 0;
    if (warp == 0 && lane < NG) {
        asm volatile("ld.relaxed.gpu.u32 %0, [%1];"
                     : "=r"(memb_base) : "l"(&g_flags[grp * 32 + lane]));
    }
    if (tid == 0) {
        asm volatile("ld.relaxed.gpu.u32 %0, [%1];" : "=r"(my_base) : "l"(myflag));
    }
    group_barrier_atomic(grp, NG);

    for (int s = 0; s < 512; s++) {
        int t = dir ? (511 - s) : s;

        const float* xpt = xp + (size_t)t * 1024 * 256;
        float xg[4][2];
#pragma unroll
        for (int g = 0; g < 4; g++) {
            xg[g][0] = xpt[(size_t)(g * 256 + u0 + 2 * j) * 256 + b0 + ub];
            xg[g][1] = xpt[(size_t)(g * 256 + u0 + 2 * j + 1) * 256 + b0 + ub];
        }

        float acc[2][4];
#pragma unroll
        for (int bi = 0; bi < 2; bi++)
#pragma unroll
            for (int r = 0; r < 4; r++) acc[bi][r] = 0.0f;

        if (s > 0) {
            if (warp == 0 && lane < NG) {
                unsigned v;
                unsigned* fp = &g_flags[grp * 32 + lane];
                do {
                    asm volatile("ld.acquire.gpu.u32 %0, [%1];" : "=r"(v) : "l"(fp));
                } while ((v - memb_base) < (unsigned)s);
            }
            __syncthreads();

            int tp = dir ? (t + 1) : (t - 1);
            size_t hbase = ((size_t)tp * NDIR + dir) * (128 * 256);
#pragma unroll
            for (int q = 0; q < 2; q++) {
                int i = tid + 512 * q;
                int kp = i >> 3, qq = (i & 7) * 4;
                *(uint4*)&H2hi[kp * HS2B + qq] =
                    *(const uint4*)&hhi[hbase + (size_t)kp * 256 + b0 + qq];
                *(uint4*)&H2lo[kp * HS2B + qq] =
                    *(const uint4*)&hlo[hbase + (size_t)kp * 256 + b0 + qq];
            }
            __syncthreads();

#pragma unroll 4
            for (int ch = 0; ch < 16; ch++) {
                int kk2 = ch * 8;
                uint32_t ahi[4], alo[4];
                int ra = (rbase + lr) * WS2 + kk2 + lc;
                ahi[0] = W2hi[ra];            ahi[2] = W2hi[ra + 4];
                ahi[1] = W2hi[ra + 8 * WS2];  ahi[3] = W2hi[ra + 8 * WS2 + 4];
                alo[0] = W2lo[ra];            alo[2] = W2lo[ra + 4];
                alo[1] = W2lo[ra + 8 * WS2];  alo[3] = W2lo[ra + 8 * WS2 + 4];
#pragma unroll
                for (int bi = 0; bi < 2; bi++) {
                    int bcol = bbase + bi * 8 + lr;
                    uint32_t bhi[2], blo[2];
                    bhi[0] = H2hi[(kk2 + lc) * HS2B + bcol];
                    bhi[1] = H2hi[(kk2 + lc + 4) * HS2B + bcol];
                    blo[0] = H2lo[(kk2 + lc) * HS2B + bcol];
                    blo[1] = H2lo[(kk2 + lc + 4) * HS2B + bcol];
                    mma_bf16(acc[bi], ahi, bhi);
                    mma_bf16(acc[bi], ahi, blo);
                    mma_bf16(acc[bi], alo, bhi);
                }
            }
        }

#pragma unroll
        for (int bi = 0; bi < 2; bi++) {
            int col = bbase + bi * 8 + lc * 2;
            *(float2*)&gsh[(rbase + lr) * RGS2 + col]     = make_float2(acc[bi][0], acc[bi][1]);
            *(float2*)&gsh[(rbase + lr + 8) * RGS2 + col] = make_float2(acc[bi][2], acc[bi][3]);
        }
        __syncthreads();

        float gv[4][2];
#pragma unroll
        for (int g = 0; g < 4; g++) {
            gv[g][0] = xg[g][0] + gsh[(g * 32 + 2 * j) * RGS2 + ub];
            gv[g][1] = xg[g][1] + gsh[(g * 32 + 2 * j + 1) * RGS2 + ub];
        }
        cr0 = sigm(gv[1][0]) * cr0 + sigm(gv[0][0]) * tanhf(gv[2][0]);
        cr1 = sigm(gv[1][1]) * cr1 + sigm(gv[0][1]) * tanhf(gv[2][1]);
        float h0 = sigm(gv[3][0]) * tanhf(cr0);
        float h1 = sigm(gv[3][1]) * tanhf(cr1);

        uint32_t hiw = packbf2(h0, h1);
        __nv_bfloat162 hb = *(__nv_bfloat162*)&hiw;
        uint32_t low = packbf2(h0 - __low2float(hb), h1 - __high2float(hb));
        size_t kidx = ((size_t)t * NDIR + dir) * (128 * 256) +
                      (size_t)(u0 / 2 + j) * 256 + b0 + ub;
        hhi[kidx] = hiw;
        hlo[kidx] = low;

        if (NDIR == 2 || t == 511) {
            float o0 = (NDIR == 2) ? __uint_as_float(f2tf32(h0)) : h0;
            float o1 = (NDIR == 2) ? __uint_as_float(f2tf32(h1)) : h1;
            size_t orow = (size_t)t * HOUT_ROWS + dir * 256 + u0 + 2 * j;
            hout[orow * 256 + b0 + ub]       = o0;
            hout[(orow + 1) * 256 + b0 + ub] = o1;
        }

        __syncthreads();
        if (tid == 0) {
            asm volatile("st.release.gpu.u32 [%0], %1;"
                         :: "l"(myflag), "r"(my_base + (unsigned)s + 1u));
        }
    }
}

// ---------------------------------------------------------------------------
__global__ void finalize_kernel(const float* __restrict__ xp1r,
                                const float* __restrict__ h1last,
                                const float* __restrict__ fc_w,
                                const float* __restrict__ fc_b,
                                float* __restrict__ out) {
    int b = blockIdx.x, u = threadIdx.x;
    float ig = xp1r[(size_t)(0   + u) * 256 + b];
    float gg = xp1r[(size_t)(512 + u) * 256 + b];
    float og = xp1r[(size_t)(768 + u) * 256 + b];
    float cc = sigm(ig) * tanhf(gg);
    float hr = sigm(og) * tanhf(cc);
    float p = fc_w[u] * h1last[(size_t)u * 256 + b] + fc_w[256 + u] * hr;
    __shared__ float red[256];
    red[u] = p;
    __syncthreads();
    for (int off = 128; off > 0; off >>= 1) {
        if (u < off) red[u] += red[u + off];
        __syncthreads();
    }
    if (u == 0) out[b] = red[0] + fc_b[0];
}

// ---------------------------------------------------------------------------
extern "C" void kernel_launch(void* const* d_in, const int* in_sizes, int n_in,
                              void* d_out, int out_size) {
    const float* x        = (const float*)d_in[0];
    const float* w_ih_l0  = (const float*)d_in[1];
    const float* w_hh_l0  = (const float*)d_in[2];
    const float* b_ih_l0  = (const float*)d_in[3];
    const float* b_hh_l0  = (const float*)d_in[4];
    const float* w_ih_l0r = (const float*)d_in[5];
    const float* w_hh_l0r = (const float*)d_in[6];
    const float* b_ih_l0r = (const float*)d_in[7];
    const float* b_hh_l0r = (const float*)d_in[8];
    const float* w_ih_l1  = (const float*)d_in[9];
    const float* w_hh_l1  = (const float*)d_in[10];
    const float* b_ih_l1  = (const float*)d_in[11];
    const float* b_hh_l1  = (const float*)d_in[12];
    const float* w_ih_l1r = (const float*)d_in[13];
    const float* b_ih_l1r = (const float*)d_in[15];
    const float* b_hh_l1r = (const float*)d_in[16];
    const float* fc_w     = (const float*)d_in[17];
    const float* fc_b     = (const float*)d_in[18];
    float* out = (float*)d_out;
    (void)in_sizes; (void)n_in; (void)out_size;

    float *xT, *xp0f, *xp0r, *h0c, *xp1f, *xp1r, *h1, *wt;
    uint32_t *hhi, *hlo;
    cudaGetSymbolAddress((void**)&xT,   g_xT);
    cudaGetSymbolAddress((void**)&xp0f, g_xp0f);
    cudaGetSymbolAddress((void**)&xp0r, g_xp0r);
    cudaGetSymbolAddress((void**)&h0c,  g_h0c);
    cudaGetSymbolAddress((void**)&xp1f, g_xp1f);
    cudaGetSymbolAddress((void**)&xp1r, g_xp1r);
    cudaGetSymbolAddress((void**)&h1,   g_h1);
    cudaGetSymbolAddress((void**)&wt,   g_wt);
    cudaGetSymbolAddress((void**)&hhi,  g_hhi);
    cudaGetSymbolAddress((void**)&hlo,  g_hlo);

    float* wt_l0  = wt;
    float* wt_l0r = wt + 1024 * 64;
    float* wt_l1  = wt + 1024 * 128;
    float* wt_l1r = wt + 1024 * 128 + 1024 * 512;

    const int REC_SMEM = (128 * WS2 * 2 + 128 * HS2B * 2 + 128 * RGS2) * 4;  // 194560
    cudaFuncSetAttribute((const void*)lstm_rec_mma<2>,
                         cudaFuncAttributeMaxDynamicSharedMemorySize, REC_SMEM);
    cudaFuncSetAttribute((const void*)lstm_rec_mma<1>,
                         cudaFuncAttributeMaxDynamicSharedMemorySize, REC_SMEM);
    cudaFuncSetAttribute((const void*)gemm_tf32,
                         cudaFuncAttributeMaxDynamicSharedMemorySize, GEMM_SMEM);

    // weight pre-conversion (tiny)
    cvt_tf32<<<(1024 * 64  + 255) / 256, 256>>>(w_ih_l0,  wt_l0,  1024 * 64);
    cvt_tf32<<<(1024 * 64  + 255) / 256, 256>>>(w_ih_l0r, wt_l0r, 1024 * 64);
    cvt_tf32<<<(1024 * 512 + 255) / 256, 256>>>(w_ih_l1,  wt_l1,  1024 * 512);
    cvt_tf32<<<(1024 * 512 + 255) / 256, 256>>>(w_ih_l1r, wt_l1r, 1024 * 512);

    transpose_x<<<dim3(1024, 8), dim3(32, 8)>>>(x, xT);
    gemm_tf32<<<dim3(8, 2, 512), 512, GEMM_SMEM>>>(xT, wt_l0,  b_ih_l0,  b_hh_l0,  xp0f, 64, 1024);
    gemm_tf32<<<dim3(8, 2, 512), 512, GEMM_SMEM>>>(xT, wt_l0r, b_ih_l0r, b_hh_l0r, xp0r, 64, 1024);
    lstm_rec_mma<2><<<128, 512, REC_SMEM>>>(xp0f, xp0r, w_hh_l0, w_hh_l0r, h0c, hhi, hlo);
    gemm_tf32<<<dim3(8, 2, 512), 512, GEMM_SMEM>>>(h0c, wt_l1, b_ih_l1, b_hh_l1, xp1f, 512, 1024);
    gemm_tf32<<<dim3(8, 2, 1), 512, GEMM_SMEM>>>(h0c + (size_t)511 * 512 * 256,
                                                 wt_l1r, b_ih_l1r, b_hh_l1r, xp1r, 512, 1024);
    lstm_rec_mma<1><<<64, 512, REC_SMEM>>>(xp1f, xp1f, w_hh_l1, w_hh_l1, h1, hhi, hlo);
    finalize_kernel<<<256, 256>>>(xp1r, h1 + (size_t)511 * 256 * 256, fc_w, fc_b, out);
}

// round 17
// speedup vs baseline: 1.1418x; 1.1418x over previous
#include <cuda_runtime.h>
#include <cuda_bf16.h>
#include <cuda_fp16.h>
#include <cstdint>

// ---------------------------------------------------------------------------
// B=256, T=512, I=64, H=256, 2-layer bidirectional LSTM, FC on last timestep.
// R17: tcgen05 unavailable (harness lowers via compute_103 PTX). GEMMs moved
//      to fp16 m16n8k16 single-term (same 11-bit mantissa as tf32, 2x MACs
//      per instruction). All GEMM operands pre-packed as half2 k-pairs;
//      L0 recurrence emits h directly as fp16 pairs (f32 h0c deleted).
// ---------------------------------------------------------------------------

__device__ float    g_xp0f[512 * 1024 * 256];
__device__ float    g_xp0r[512 * 1024 * 256];
__device__ float    g_xp1f[512 * 1024 * 256];
__device__ float    g_xp1r[1024 * 256];
__device__ float    g_h1  [512 * 256 * 256];
__device__ uint32_t g_hhi [512 * 2 * 128 * 256];   // h bf16x2 hi (recurrence exchange)
__device__ uint32_t g_hlo [512 * 2 * 128 * 256];   // h bf16x2 lo
__device__ uint32_t g_x16 [16384 * 256];           // x packed half2 [fpair][b]
__device__ uint32_t g_h16 [512 * 256 * 256];       // h0c packed half2 [t][kpair][b]
__device__ uint32_t g_w16 [2 * 32768 + 2 * 262144];// packed half2 W_ih's [n][kpair]

__device__ unsigned g_gcnt [32 * 32];
__device__ unsigned g_ggen [32 * 32];
__device__ unsigned g_flags[16 * 32];

__device__ __forceinline__ float sigm(float x) { return 1.0f / (1.0f + __expf(-x)); }

__device__ __forceinline__ void mma_bf16(float c[4], const uint32_t a[4], const uint32_t b[2]) {
    asm volatile(
        "mma.sync.aligned.m16n8k16.row.col.f32.bf16.bf16.f32 "
        "{%0,%1,%2,%3}, {%4,%5,%6,%7}, {%8,%9}, {%0,%1,%2,%3};"
        : "+f"(c[0]), "+f"(c[1]), "+f"(c[2]), "+f"(c[3])
        : "r"(a[0]), "r"(a[1]), "r"(a[2]), "r"(a[3]), "r"(b[0]), "r"(b[1]));
}

__device__ __forceinline__ void mma_fp16(float c[4], const uint32_t a[4], const uint32_t b[2]) {
    asm volatile(
        "mma.sync.aligned.m16n8k16.row.col.f32.f16.f16.f32 "
        "{%0,%1,%2,%3}, {%4,%5,%6,%7}, {%8,%9}, {%0,%1,%2,%3};"
        : "+f"(c[0]), "+f"(c[1]), "+f"(c[2]), "+f"(c[3])
        : "r"(a[0]), "r"(a[1]), "r"(a[2]), "r"(a[3]), "r"(b[0]), "r"(b[1]));
}

__device__ __forceinline__ uint32_t packbf2(float a, float b) {
    __nv_bfloat162 t = __floats2bfloat162_rn(a, b);
    return *(uint32_t*)&t;
}
__device__ __forceinline__ uint32_t packhf2(float a, float b) {
    __half2 t = __floats2half2_rn(a, b);
    return *(uint32_t*)&t;
}

__device__ __forceinline__ void cp_async16(void* smem_dst, const void* gptr) {
    uint32_t sa = (uint32_t)__cvta_generic_to_shared(smem_dst);
    asm volatile("cp.async.cg.shared.global [%0], [%1], 16;" :: "r"(sa), "l"(gptr));
}
__device__ __forceinline__ void cp_commit() { asm volatile("cp.async.commit_group;"); }
template <int N>
__device__ __forceinline__ void cp_wait() { asm volatile("cp.async.wait_group %0;" :: "n"(N)); }

// Proven acquire/release atomic group barrier — used ONCE per launch.
__device__ __forceinline__ void group_barrier_atomic(int grp, unsigned members) {
    __syncthreads();
    if (threadIdx.x == 0) {
        unsigned* cnt = &g_gcnt[grp * 32];
        unsigned* gen = &g_ggen[grp * 32];
        unsigned g0;
        asm volatile("ld.acquire.gpu.u32 %0, [%1];" : "=r"(g0) : "l"(gen));
        unsigned old;
        asm volatile("atom.acq_rel.gpu.add.u32 %0, [%1], 1;" : "=r"(old) : "l"(cnt));
        if (old == members - 1) {
            asm volatile("st.relaxed.gpu.u32 [%0], %1;" :: "l"(cnt), "r"(0u));
            asm volatile("red.release.gpu.add.u32 [%0], %1;" :: "l"(gen), "r"(1u));
        } else {
            unsigned g1;
            do {
                asm volatile("ld.acquire.gpu.u32 %0, [%1];" : "=r"(g1) : "l"(gen));
            } while (g1 == g0);
        }
    }
    __syncthreads();
}

// ---------------------------------------------------------------------------
// Weight pre-pack: out[i] = half2(in[2i], in[2i+1])  (row-major pairwise)
// ---------------------------------------------------------------------------
__global__ void cvt_w16(const float* __restrict__ in, uint32_t* __restrict__ out, int np) {
    int i = blockIdx.x * 256 + threadIdx.x;
    if (i < np) {
        float2 v = *(const float2*)&in[2 * i];
        out[i] = packhf2(v.x, v.y);
    }
}

// ---------------------------------------------------------------------------
// x[b][f] (f = t*64+k) -> x16[fp][b] = half2(x[b][2fp], x[b][2fp+1])
// block 32x8: tile 32 b x 64 f. grid (512, 8).
// ---------------------------------------------------------------------------
__global__ void transpose_x16(const float* __restrict__ x, uint32_t* __restrict__ x16) {
    __shared__ float tile[32][65];
    int f0 = blockIdx.x * 64, b0 = blockIdx.y * 32;
    int tx = threadIdx.x, ty = threadIdx.y;
#pragma unroll
    for (int i = 0; i < 4; i++) {
        float2 v = *(const float2*)&x[(size_t)(b0 + ty + 8 * i) * 32768 + f0 + 2 * tx];
        tile[ty + 8 * i][2 * tx]     = v.x;
        tile[ty + 8 * i][2 * tx + 1] = v.y;
    }
    __syncthreads();
#pragma unroll
    for (int i = 0; i < 4; i++) {
        int fp = ty + 8 * i;   // 0..31 pair index within tile
        x16[(size_t)(f0 / 2 + fp) * 256 + b0 + tx] =
            packhf2(tile[tx][2 * fp], tile[tx][2 * fp + 1]);
    }
}

// ---------------------------------------------------------------------------
// fp16 GEMM: C[t][n][b] = sum_k W[n][k]*Act[t][k][b] + b1[n] + b2[n]
// act16: [t][KP kpairs][256 b] half2; w16: [n][KP] half2. KP = K/2.
// grid (8 n-tiles, 2 m-tiles, T), 256 threads, warp tile 64n x 32b,
// 3-stage cp.async pipeline, 8 kpairs (16 k) per iteration.
// ---------------------------------------------------------------------------
#define WH_S 12    // Wh row stride (8 kp + pad) -> conflict-free a-frags
#define AH_S 132   // Ah row stride (128 b + pad)
#define G16_SMEM ((3 * 128 * WH_S + 3 * 8 * AH_S) * 4)   // 31104 B

__global__ void gemm_fp16(const uint32_t* __restrict__ act16, const uint32_t* __restrict__ w16,
                          const float* __restrict__ b1, const float* __restrict__ b2,
                          float* __restrict__ C, int KP) {
    extern __shared__ uint32_t gsm[];
    uint32_t* WhB = gsm;                       // [3][128*12]
    uint32_t* AhB = gsm + 3 * 128 * WH_S;      // [3][8*132]

    int t  = blockIdx.z;
    int n0 = blockIdx.x * 128, m0 = blockIdx.y * 128;
    const uint32_t* At = act16 + (size_t)t * KP * 256 + m0;
    const uint32_t* Wt = w16 + (size_t)n0 * KP;
    float* Ct = C + (size_t)t * 1024 * 256;

    int tid = threadIdx.x;
    int warp = tid >> 5, lane = tid & 31;
    int wn = (warp >> 2) * 64;
    int wb = (warp & 3) * 32;
    int lr = lane >> 2, lc = lane & 3;

    // staging maps (full coverage, 16B-aligned)
    int a_kp = tid >> 5, a_b4 = (tid & 31) * 4;   // Ah: 8 kp x 128 b
    int w_n  = tid >> 1, w_k4 = (tid & 1) * 4;    // Wh: 128 n x 8 kp

    float acc[4][4][4];
#pragma unroll
    for (int i = 0; i < 4; i++)
#pragma unroll
        for (int jj = 0; jj < 4; jj++)
#pragma unroll
            for (int r = 0; r < 4; r++) acc[i][jj][r] = 0.0f;

    auto stage = [&](int buf, int kp0) {
        uint32_t* Ahb = AhB + buf * 8 * AH_S;
        uint32_t* Whb = WhB + buf * 128 * WH_S;
        cp_async16(&Ahb[a_kp * AH_S + a_b4],
                   &At[(size_t)(kp0 + a_kp) * 256 + a_b4]);
        cp_async16(&Whb[w_n * WH_S + w_k4],
                   &Wt[(size_t)w_n * KP + kp0 + w_k4]);
    };

    int niter = KP / 8;
    stage(0, 0);
    cp_commit();
    if (niter > 1) { stage(1, 8); cp_commit(); }

    for (int it = 0; it < niter; it++) {
        int buf = it % 3;
        if (it + 1 < niter) cp_wait<1>(); else cp_wait<0>();
        __syncthreads();

        uint32_t* Ahb = AhB + buf * 8 * AH_S;
        uint32_t* Whb = WhB + buf * 128 * WH_S;
        uint32_t a[4][4], b[4][2];
#pragma unroll
        for (int ni = 0; ni < 4; ni++) {
            int n = wn + ni * 16 + lr;
            a[ni][0] = Whb[n * WH_S + lc];
            a[ni][1] = Whb[(n + 8) * WH_S + lc];
            a[ni][2] = Whb[n * WH_S + lc + 4];
            a[ni][3] = Whb[(n + 8) * WH_S + lc + 4];
        }
#pragma unroll
        for (int bi = 0; bi < 4; bi++) {
            int bb = wb + bi * 8 + lr;
            b[bi][0] = Ahb[lc * AH_S + bb];
            b[bi][1] = Ahb[(lc + 4) * AH_S + bb];
        }
#pragma unroll
        for (int ni = 0; ni < 4; ni++)
#pragma unroll
            for (int bi = 0; bi < 4; bi++)
                mma_fp16(acc[ni][bi], a[ni], b[bi]);

        if (it + 2 < niter) {
            stage((it + 2) % 3, (it + 2) * 8);
            cp_commit();
        }
    }

#pragma unroll
    for (int ni = 0; ni < 4; ni++) {
#pragma unroll
        for (int h = 0; h < 2; h++) {
            int n = n0 + wn + ni * 16 + lr + h * 8;
            float bias = b1[n] + b2[n];
#pragma unroll
            for (int bi = 0; bi < 4; bi++) {
                int bb = m0 + wb + bi * 8 + lc * 2;
                float2 v = make_float2(acc[ni][bi][h * 2] + bias,
                                       acc[ni][bi][h * 2 + 1] + bias);
                *(float2*)&Ct[(size_t)n * 256 + bb] = v;
            }
        }
    }
}

// ---------------------------------------------------------------------------
// bf16 tensor-core persistent recurrence (proven R12/R14 version).
// NDIR==2: h emitted as fp16 pairs into h16 (feeds next-layer fp16 GEMM).
// NDIR==1: f32 h stored only at t=511 (FC head).
// ---------------------------------------------------------------------------
#define WS2  132
#define HS2B 40
#define RGS2 36

template <int NDIR>
__global__ void __launch_bounds__(512, 1)
lstm_rec_mma(const float* __restrict__ xp_f, const float* __restrict__ xp_r,
             const float* __restrict__ whh_f, const float* __restrict__ whh_r,
             float* __restrict__ hout, uint32_t* __restrict__ h16,
             uint32_t* __restrict__ hhi, uint32_t* __restrict__ hlo) {
    constexpr int NG = 8, BGN = 8;

    extern __shared__ char smraw[];
    uint32_t* W2hi = (uint32_t*)smraw;
    uint32_t* W2lo = W2hi + 128 * WS2;
    uint32_t* H2hi = W2lo + 128 * WS2;
    uint32_t* H2lo = H2hi + 128 * HS2B;
    float*    gsh  = (float*)(H2lo + 128 * HS2B);

    int tid = threadIdx.x;
    int bx  = blockIdx.x;
    int dir = (NDIR == 2) ? (bx / (NG * BGN)) : 0;
    int rem = bx % (NG * BGN);
    int ng = rem / BGN, bg = rem % BGN;
    int u0 = ng * 32, b0 = bg * 32;
    int grp = dir * BGN + bg;

    const float* xp  = dir ? xp_r : xp_f;
    const float* whh = dir ? whh_r : whh_f;

    for (int i = tid; i < 128 * 128; i += 512) {
        int r = i >> 7, kp = i & 127;
        int grow = (r >> 5) * 256 + u0 + (r & 31);
        float2 w = *(const float2*)&whh[(size_t)grow * 256 + 2 * kp];
        uint32_t hi = packbf2(w.x, w.y);
        __nv_bfloat162 hb = *(__nv_bfloat162*)&hi;
        W2hi[r * WS2 + kp] = hi;
        W2lo[r * WS2 + kp] = packbf2(w.x - __low2float(hb), w.y - __high2float(hb));
    }

    int warp = tid >> 5, lane = tid & 31;
    int rbase = (warp & 7) * 16;
    int bbase = (warp >> 3) * 16;
    int lr = lane >> 2, lc = lane & 3;

    int j  = tid >> 5;
    int ub = tid & 31;
    float cr0 = 0.f, cr1 = 0.f;

    unsigned* myflag = &g_flags[grp * 32 + ng];
    unsigned memb_base = 0, my_base = 0;
    if (warp == 0 && lane < NG) {
        asm volatile("ld.relaxed.gpu.u32 %0, [%1];"
                     : "=r"(memb_base) : "l"(&g_flags[grp * 32 + lane]));
    }
    if (tid == 0) {
        asm volatile("ld.relaxed.gpu.u32 %0, [%1];" : "=r"(my_base) : "l"(myflag));
    }
    group_barrier_atomic(grp, NG);

    for (int s = 0; s < 512; s++) {
        int t = dir ? (511 - s) : s;

        const float* xpt = xp + (size_t)t * 1024 * 256;
        float xg[4][2];
#pragma unroll
        for (int g = 0; g < 4; g++) {
            xg[g][0] = xpt[(size_t)(g * 256 + u0 + 2 * j) * 256 + b0 + ub];
            xg[g][1] = xpt[(size_t)(g * 256 + u0 + 2 * j + 1) * 256 + b0 + ub];
        }

        float acc[2][4];
#pragma unroll
        for (int bi = 0; bi < 2; bi++)
#pragma unroll
            for (int r = 0; r < 4; r++) acc[bi][r] = 0.0f;

        if (s > 0) {
            if (warp == 0 && lane < NG) {
                unsigned v;
                unsigned* fp = &g_flags[grp * 32 + lane];
                do {
                    asm volatile("ld.acquire.gpu.u32 %0, [%1];" : "=r"(v) : "l"(fp));
                } while ((v - memb_base) < (unsigned)s);
            }
            __syncthreads();

            int tp = dir ? (t + 1) : (t - 1);
            size_t hbase = ((size_t)tp * NDIR + dir) * (128 * 256);
#pragma unroll
            for (int q = 0; q < 2; q++) {
                int i = tid + 512 * q;
                int kp = i >> 3, qq = (i & 7) * 4;
                *(uint4*)&H2hi[kp * HS2B + qq] =
                    *(const uint4*)&hhi[hbase + (size_t)kp * 256 + b0 + qq];
                *(uint4*)&H2lo[kp * HS2B + qq] =
                    *(const uint4*)&hlo[hbase + (size_t)kp * 256 + b0 + qq];
            }
            __syncthreads();

#pragma unroll 4
            for (int ch = 0; ch < 16; ch++) {
                int kk2 = ch * 8;
                uint32_t ahi[4], alo[4];
                int ra = (rbase + lr) * WS2 + kk2 + lc;
                ahi[0] = W2hi[ra];            ahi[2] = W2hi[ra + 4];
                ahi[1] = W2hi[ra + 8 * WS2];  ahi[3] = W2hi[ra + 8 * WS2 + 4];
                alo[0] = W2lo[ra];            alo[2] = W2lo[ra + 4];
                alo[1] = W2lo[ra + 8 * WS2];  alo[3] = W2lo[ra + 8 * WS2 + 4];
#pragma unroll
                for (int bi = 0; bi < 2; bi++) {
                    int bcol = bbase + bi * 8 + lr;
                    uint32_t bhi[2], blo[2];
                    bhi[0] = H2hi[(kk2 + lc) * HS2B + bcol];
                    bhi[1] = H2hi[(kk2 + lc + 4) * HS2B + bcol];
                    blo[0] = H2lo[(kk2 + lc) * HS2B + bcol];
                    blo[1] = H2lo[(kk2 + lc + 4) * HS2B + bcol];
                    mma_bf16(acc[bi], ahi, bhi);
                    mma_bf16(acc[bi], ahi, blo);
                    mma_bf16(acc[bi], alo, bhi);
                }
            }
        }

#pragma unroll
        for (int bi = 0; bi < 2; bi++) {
            int col = bbase + bi * 8 + lc * 2;
            *(float2*)&gsh[(rbase + lr) * RGS2 + col]     = make_float2(acc[bi][0], acc[bi][1]);
            *(float2*)&gsh[(rbase + lr + 8) * RGS2 + col] = make_float2(acc[bi][2], acc[bi][3]);
        }
        __syncthreads();

        float gv[4][2];
#pragma unroll
        for (int g = 0; g < 4; g++) {
            gv[g][0] = xg[g][0] + gsh[(g * 32 + 2 * j) * RGS2 + ub];
            gv[g][1] = xg[g][1] + gsh[(g * 32 + 2 * j + 1) * RGS2 + ub];
        }
        cr0 = sigm(gv[1][0]) * cr0 + sigm(gv[0][0]) * tanhf(gv[2][0]);
        cr1 = sigm(gv[1][1]) * cr1 + sigm(gv[0][1]) * tanhf(gv[2][1]);
        float h0 = sigm(gv[3][0]) * tanhf(cr0);
        float h1 = sigm(gv[3][1]) * tanhf(cr1);

        // bf16 hi/lo for next-step recurrence consumers
        uint32_t hiw = packbf2(h0, h1);
        __nv_bfloat162 hb = *(__nv_bfloat162*)&hiw;
        uint32_t low = packbf2(h0 - __low2float(hb), h1 - __high2float(hb));
        size_t kidx = ((size_t)t * NDIR + dir) * (128 * 256) +
                      (size_t)(u0 / 2 + j) * 256 + b0 + ub;
        hhi[kidx] = hiw;
        hlo[kidx] = low;

        if (NDIR == 2) {
            // fp16 pair store for the next layer's fp16 GEMM (k = dir*256+unit)
            int kpg = dir * 128 + u0 / 2 + j;
            h16[((size_t)t * 256 + kpg) * 256 + b0 + ub] = packhf2(h0, h1);
        } else if (t == 511) {
            size_t orow = (size_t)t * 256 + u0 + 2 * j;
            hout[orow * 256 + b0 + ub]       = h0;
            hout[(orow + 1) * 256 + b0 + ub] = h1;
        }

        __syncthreads();
        if (tid == 0) {
            asm volatile("st.release.gpu.u32 [%0], %1;"
                         :: "l"(myflag), "r"(my_base + (unsigned)s + 1u));
        }
    }
}

// ---------------------------------------------------------------------------
__global__ void finalize_kernel(const float* __restrict__ xp1r,
                                const float* __restrict__ h1last,
                                const float* __restrict__ fc_w,
                                const float* __restrict__ fc_b,
                                float* __restrict__ out) {
    int b = blockIdx.x, u = threadIdx.x;
    float ig = xp1r[(size_t)(0   + u) * 256 + b];
    float gg = xp1r[(size_t)(512 + u) * 256 + b];
    float og = xp1r[(size_t)(768 + u) * 256 + b];
    float cc = sigm(ig) * tanhf(gg);
    float hr = sigm(og) * tanhf(cc);
    float p = fc_w[u] * h1last[(size_t)u * 256 + b] + fc_w[256 + u] * hr;
    __shared__ float red[256];
    red[u] = p;
    __syncthreads();
    for (int off = 128; off > 0; off >>= 1) {
        if (u < off) red[u] += red[u + off];
        __syncthreads();
    }
    if (u == 0) out[b] = red[0] + fc_b[0];
}

// ---------------------------------------------------------------------------
extern "C" void kernel_launch(void* const* d_in, const int* in_sizes, int n_in,
                              void* d_out, int out_size) {
    const float* x        = (const float*)d_in[0];
    const float* w_ih_l0  = (const float*)d_in[1];
    const float* w_hh_l0  = (const float*)d_in[2];
    const float* b_ih_l0  = (const float*)d_in[3];
    const float* b_hh_l0  = (const float*)d_in[4];
    const float* w_ih_l0r = (const float*)d_in[5];
    const float* w_hh_l0r = (const float*)d_in[6];
    const float* b_ih_l0r = (const float*)d_in[7];
    const float* b_hh_l0r = (const float*)d_in[8];
    const float* w_ih_l1  = (const float*)d_in[9];
    const float* w_hh_l1  = (const float*)d_in[10];
    const float* b_ih_l1  = (const float*)d_in[11];
    const float* b_hh_l1  = (const float*)d_in[12];
    const float* w_ih_l1r = (const float*)d_in[13];
    const float* b_ih_l1r = (const float*)d_in[15];
    const float* b_hh_l1r = (const float*)d_in[16];
    const float* fc_w     = (const float*)d_in[17];
    const float* fc_b     = (const float*)d_in[18];
    float* out = (float*)d_out;
    (void)in_sizes; (void)n_in; (void)out_size;

    float *xp0f, *xp0r, *xp1f, *xp1r, *h1;
    uint32_t *hhi, *hlo, *x16, *h16, *w16;
    cudaGetSymbolAddress((void**)&xp0f, g_xp0f);
    cudaGetSymbolAddress((void**)&xp0r, g_xp0r);
    cudaGetSymbolAddress((void**)&xp1f, g_xp1f);
    cudaGetSymbolAddress((void**)&xp1r, g_xp1r);
    cudaGetSymbolAddress((void**)&h1,   g_h1);
    cudaGetSymbolAddress((void**)&hhi,  g_hhi);
    cudaGetSymbolAddress((void**)&hlo,  g_hlo);
    cudaGetSymbolAddress((void**)&x16,  g_x16);
    cudaGetSymbolAddress((void**)&h16,  g_h16);
    cudaGetSymbolAddress((void**)&w16,  g_w16);

    uint32_t* w16_l0  = w16;
    uint32_t* w16_l0r = w16 + 32768;
    uint32_t* w16_l1  = w16 + 65536;
    uint32_t* w16_l1r = w16 + 65536 + 262144;

    const int REC_SMEM = (128 * WS2 * 2 + 128 * HS2B * 2 + 128 * RGS2) * 4;  // 194560
    cudaFuncSetAttribute((const void*)lstm_rec_mma<2>,
                         cudaFuncAttributeMaxDynamicSharedMemorySize, REC_SMEM);
    cudaFuncSetAttribute((const void*)lstm_rec_mma<1>,
                         cudaFuncAttributeMaxDynamicSharedMemorySize, REC_SMEM);
    cudaFuncSetAttribute((const void*)gemm_fp16,
                         cudaFuncAttributeMaxDynamicSharedMemorySize, G16_SMEM);

    // weight pre-pack (tiny)
    cvt_w16<<<(32768  + 255) / 256, 256>>>(w_ih_l0,  w16_l0,  32768);
    cvt_w16<<<(32768  + 255) / 256, 256>>>(w_ih_l0r, w16_l0r, 32768);
    cvt_w16<<<(262144 + 255) / 256, 256>>>(w_ih_l1,  w16_l1,  262144);
    cvt_w16<<<(262144 + 255) / 256, 256>>>(w_ih_l1r, w16_l1r, 262144);

    transpose_x16<<<dim3(512, 8), dim3(32, 8)>>>(x, x16);
    gemm_fp16<<<dim3(8, 2, 512), 256, G16_SMEM>>>(x16, w16_l0,  b_ih_l0,  b_hh_l0,  xp0f, 32);
    gemm_fp16<<<dim3(8, 2, 512), 256, G16_SMEM>>>(x16, w16_l0r, b_ih_l0r, b_hh_l0r, xp0r, 32);
    lstm_rec_mma<2><<<128, 512, REC_SMEM>>>(xp0f, xp0r, w_hh_l0, w_hh_l0r,
                                            h1 /*unused*/, h16, hhi, hlo);
    gemm_fp16<<<dim3(8, 2, 512), 256, G16_SMEM>>>(h16, w16_l1, b_ih_l1, b_hh_l1, xp1f, 256);
    gemm_fp16<<<dim3(8, 2, 1), 256, G16_SMEM>>>(h16 + (size_t)511 * 256 * 256,
                                                w16_l1r, b_ih_l1r, b_hh_l1r, xp1r, 256);
    lstm_rec_mma<1><<<64, 512, REC_SMEM>>>(xp1f, xp1f, w_hh_l1, w_hh_l1,
                                           h1, h16 /*unused*/, hhi, hlo);
    finalize_kernel<<<256, 256>>>(xp1r, h1 + (size_t)511 * 256 * 256, fc_w, fc_b, out);
}